// round 14
// baseline (speedup 1.0000x reference)
#include <cuda_runtime.h>
#include <cuda_fp16.h>
#include <math.h>
#include <stdint.h>

#define BB 2048
#define TT 128
#define DD 32
#define HH 256
#define SS 39
#define PMM 12
#define KR 288              /* k layout: [h 256 | x 32] */
#define NCHUNK 2
#define KB 144
#define NK16 18             /* 288/16 */

/* smem layout (bytes) */
#define A_PITCH 304                       /* 152 halfs: 144 data + 8 pad, odd x 16B */
#define A_STAGE (128 * A_PITCH)           /* 38912 */
#define W_ORIGIN (2 * A_STAGE)            /* 77824 */
#define W_PITCH 208                       /* 104 halfs: 96 data + 8 pad */
#define SMEM_TOTAL (W_ORIGIN + KR * W_PITCH)   /* 137728 */

// ---------------- device scratch ----------------
__device__ __half g_X[2][BB * KR];               // activations [b][k], ping-pong
__device__ float g_weff[HH + PMM];
__device__ float g_beff;

// ---------------- asm helpers ----------------
__device__ __forceinline__ uint32_t smem_u32(const void* p) {
    uint32_t a;
    asm("{ .reg .u64 t; cvta.to.shared.u64 t, %1; cvt.u32.u64 %0, t; }" : "=r"(a) : "l"(p));
    return a;
}
__device__ __forceinline__ void cp16(uint32_t dst, const void* src) {
    asm volatile("cp.async.cg.shared.global [%0], [%1], 16;" :: "r"(dst), "l"(src) : "memory");
}
__device__ __forceinline__ void cp_commit() {
    asm volatile("cp.async.commit_group;" ::: "memory");
}
template <int N>
__device__ __forceinline__ void cp_wait() {
    asm volatile("cp.async.wait_group %0;" :: "n"(N) : "memory");
}
__device__ __forceinline__ void ldm_x4(uint32_t* r, uint32_t addr) {
    asm volatile("ldmatrix.sync.aligned.m8n8.x4.shared.b16 {%0,%1,%2,%3}, [%4];"
                 : "=r"(r[0]), "=r"(r[1]), "=r"(r[2]), "=r"(r[3]) : "r"(addr));
}
__device__ __forceinline__ void ldm_x2t(uint32_t* r, uint32_t addr) {
    asm volatile("ldmatrix.sync.aligned.m8n8.x2.trans.shared.b16 {%0,%1}, [%2];"
                 : "=r"(r[0]), "=r"(r[1]) : "r"(addr));
}
__device__ __forceinline__ void mma16816(float* d, const uint32_t* a, const uint32_t* b) {
    asm volatile(
        "mma.sync.aligned.m16n8k16.row.col.f32.f16.f16.f32 "
        "{%0,%1,%2,%3}, {%4,%5,%6,%7}, {%8,%9}, {%0,%1,%2,%3};"
        : "+f"(d[0]), "+f"(d[1]), "+f"(d[2]), "+f"(d[3])
        : "r"(a[0]), "r"(a[1]), "r"(a[2]), "r"(a[3]), "r"(b[0]), "r"(b[1]));
}
__device__ __forceinline__ float tanh_fast(float x) {
    float y;
    asm("tanh.approx.f32 %0, %1;" : "=f"(y) : "f"(x));
    return y;
}
__device__ __forceinline__ float sigmoid_fast(float x) {
    return fmaf(0.5f, tanh_fast(0.5f * x), 0.5f);
}
__device__ __forceinline__ uint32_t tanh_h2(uint32_t x) {
    uint32_t y;
    asm("tanh.approx.f16x2 %0, %1;" : "=r"(y) : "r"(x));
    return y;
}
__device__ __forceinline__ uint32_t pack_h2(float a, float b) {
    __half2 h = __floats2half2_rn(a, b);
    return *(uint32_t*)&h;
}
__device__ __forceinline__ __half2 u2h(uint32_t u) { return *(__half2*)&u; }
__device__ __forceinline__ void cluster_arrive() {
    asm volatile("barrier.cluster.arrive.aligned;" ::: "memory");
}
__device__ __forceinline__ void cluster_wait() {
    asm volatile("barrier.cluster.wait.aligned;" ::: "memory");
}

// ---------------- prep: warp-parallel head collapse + out zero (34 blocks) ----------------
__global__ void prep_head(const float* __restrict__ Wd0, const float* __restrict__ bd0,
                          const float* __restrict__ Wd1, const float* __restrict__ bd1,
                          float* __restrict__ out)
{
    const int gw = blockIdx.x * 8 + (threadIdx.x >> 5);
    const int lane = threadIdx.x & 31;
    const int gid = blockIdx.x * 256 + threadIdx.x;
    if (gid < BB) out[gid] = 0.0f;
    if (gw < HH + PMM) {
        float s = 0.0f;
        #pragma unroll
        for (int i = 0; i < 8; i++) {
            int m = i * 32 + lane;
            s += Wd1[m] * Wd0[m * (HH + PMM) + gw];
        }
        #pragma unroll
        for (int off = 16; off > 0; off >>= 1)
            s += __shfl_xor_sync(0xFFFFFFFFu, s, off);
        if (lane == 0) g_weff[gw] = s;
    } else if (gw == HH + PMM) {
        float s = 0.0f;
        #pragma unroll
        for (int i = 0; i < 8; i++) {
            int m = i * 32 + lane;
            s += Wd1[m] * bd0[m];
        }
        #pragma unroll
        for (int off = 16; off > 0; off >>= 1)
            s += __shfl_xor_sync(0xFFFFFFFFu, s, off);
        if (lane == 0) g_beff = s + bd1[0];
    }
}

// ---------------- persistent recurrent kernel (8-CTA cluster per bm) ----------------
__global__ void __launch_bounds__(256, 1) __cluster_dims__(1, 8, 1) step_persist(
    const float* __restrict__ xg,
    const float* __restrict__ latlons, const float* __restrict__ yearly,
    const float* __restrict__ Wu, const float* __restrict__ bu,
    const float* __restrict__ Wf_i, const float* __restrict__ Wf_h, const float* __restrict__ bf,
    const float* __restrict__ Wg_i, const float* __restrict__ Wg_h, const float* __restrict__ bg,
    const float* __restrict__ Wo_i, const float* __restrict__ Wo_h, const float* __restrict__ bo,
    const float* __restrict__ pm, float* __restrict__ out)
{
    extern __shared__ char smem[];
    const uint32_t sb = smem_u32(smem);
    const int tid = threadIdx.x;
    const int lane = tid & 31;
    const int wid = tid >> 5;
    const int wm = wid & 1;           // 0..1 (64 batch rows)
    const int wn = wid >> 1;          // 0..3 (8 h cols)
    const int bm = blockIdx.x;        // 0..15
    const int jt = blockIdx.y;        // 0..7 (cluster rank)
    const int b_base = bm * 128;
    const int h0 = jt * 32;

    const int r_base = b_base + wm * 64 + (lane >> 2);    // + mt*16 + rr*8
    const int hcol = h0 + wn * 8 + (lane & 3) * 2;        // 2 consecutive h

    // ---- prologue: W tile gathered directly from raw fp32 weights -> SMEM ----
    {
        __half* Wrow = (__half*)(smem + W_ORIGIN);
        #pragma unroll
        for (int ci = 0; ci < 12; ci++) {
            int col = wid * 12 + ci;
            int gate = col >> 5;
            int hh = col & 31;
            const float* Whg = (gate == 0) ? Wf_h : (gate == 1) ? Wg_h : Wo_h;
            const float* Wig = (gate == 0) ? Wf_i : (gate == 1) ? Wg_i : Wo_i;
            const float* hrow = Whg + (size_t)(h0 + hh) * HH;
            const float* irow = Wig + (size_t)(h0 + hh) * DD;
            #pragma unroll
            for (int it = 0; it < 9; it++) {
                int k = it * 32 + lane;
                float v = (k < HH) ? hrow[k] : irow[k - HH];
                Wrow[k * 104 + col] = __float2half(v);
            }
        }
    }

    // ---- prologue: bias (sigmoid ones pre-scaled) + head weights ----
    float bFh[2], bG[2], bOh[2];
    #pragma unroll
    for (int cc = 0; cc < 2; cc++) {
        bFh[cc] = bf[hcol + cc] * 0.5f;
        bG[cc]  = bg[hcol + cc];
        bOh[cc] = bo[hcol + cc] * 0.5f;
    }
    const float wf0 = g_weff[hcol];
    const float wf1 = g_weff[hcol + 1];
    const __half2 h05 = __float2half2_rn(0.5f);

    // ---- prologue: i_gate into registers, c = 0 ----
    float c_r[4][2][2];
    float ig_r[4][2][2];
    #pragma unroll
    for (int mt = 0; mt < 4; mt++)
        #pragma unroll
        for (int rr = 0; rr < 2; rr++) {
            const int b = r_base + mt * 16 + rr * 8;
            const float ll0 = latlons[b * 2 + 0];
            const float ll1 = latlons[b * 2 + 1];
            const float* yr = yearly + (size_t)b * 37;
            #pragma unroll
            for (int cc = 0; cc < 2; cc++) {
                const int h = hcol + cc;
                const float* w = Wu + h * SS;
                float s = bu[h] + w[0] * ll0 + w[1] * ll1;
                #pragma unroll
                for (int i = 0; i < 37; i++) s += w[2 + i] * yr[i];
                ig_r[mt][rr][cc] = sigmoid_fast(s);
                c_r[mt][rr][cc] = 0.0f;
            }
        }

    // ---- prologue: init X[0] in place ----
    #pragma unroll
    for (int mt = 0; mt < 4; mt++)
        #pragma unroll
        for (int rr = 0; rr < 2; rr++) {
            int b = r_base + mt * 16 + rr * 8;
            *(uint32_t*)(&g_X[0][(size_t)b * KR + hcol]) = 0u;
        }
    if (jt == 0 && tid < 128) {
        const int b = b_base + tid;
        const float* xr = xg + (size_t)b * (TT * DD);
        __half* dst = &g_X[0][(size_t)b * KR + HH];
        #pragma unroll
        for (int i = 0; i < 4; i++) {
            float4 v0 = *(const float4*)(xr + i * 8);
            float4 v1 = *(const float4*)(xr + i * 8 + 4);
            uint4 pk = make_uint4(pack_h2(v0.x, v0.y), pack_h2(v0.z, v0.w),
                                  pack_h2(v1.x, v1.y), pack_h2(v1.z, v1.w));
            *(uint4*)(dst + i * 8) = pk;
        }
    }
    __syncthreads();

    // ---- hoist W fragments into registers (gate = nt) ----
    uint32_t bfrag[NK16][3][2];
    {
        const uint32_t wb = sb + W_ORIGIN + (lane & 15) * W_PITCH + wn * 16;
        #pragma unroll
        for (int k16 = 0; k16 < NK16; k16++)
            #pragma unroll
            for (int gate = 0; gate < 3; gate++)
                ldm_x2t(bfrag[k16][gate], wb + k16 * (16 * W_PITCH) + gate * 64);
    }

    // ---- cluster barrier: X[0] visible across the bm group ----
    cluster_arrive();
    cluster_wait();

    const uint32_t a_off = (uint32_t)((wm * 64 + (lane & 15)) * A_PITCH + (lane >> 4) * 16);

    for (int t = 0; t < TT; t++) {
        const __half* __restrict__ Xb = g_X[t & 1];
        __half* Xo = &g_X[(t + 1) & 1][0];

        // ---- issue both A chunks (cp.async.cg: L2-only) ----
        #pragma unroll
        for (int c = 0; c < NCHUNK; c++) {
            #pragma unroll
            for (int i = 0; i < 9; i++) {
                int slot = tid + i * 256;
                int row = slot / 18;
                int cq = slot - row * 18;
                cp16(sb + c * A_STAGE + row * A_PITCH + cq * 16,
                     Xb + (size_t)(b_base + row) * KR + c * KB + cq * 8);
            }
            cp_commit();
        }

        float acc[4][3][4];
        #pragma unroll
        for (int mt = 0; mt < 4; mt++)
            #pragma unroll
            for (int g = 0; g < 3; g++)
                #pragma unroll
                for (int q = 0; q < 4; q++) acc[mt][g][q] = 0.0f;

        // ---- MMA over 2 chunks x 9 k16 ----
        #pragma unroll
        for (int c = 0; c < NCHUNK; c++) {
            if (c == 0) cp_wait<1>();
            else cp_wait<0>();
            __syncthreads();
            const uint32_t aB = sb + c * A_STAGE + a_off;
            #pragma unroll
            for (int kk = 0; kk < 9; kk++) {
                uint32_t af[4][4];
                #pragma unroll
                for (int mt = 0; mt < 4; mt++)
                    ldm_x4(af[mt], aB + mt * (16 * A_PITCH) + kk * 32);
                #pragma unroll
                for (int mt = 0; mt < 4; mt++)
                    #pragma unroll
                    for (int g = 0; g < 3; g++)
                        mma16816(acc[mt][g], af[mt], bfrag[c * 9 + kk][g]);
            }
        }

        // ---- f16x2 epilogue: gates, state update, direct STG (or inline head) ----
        #pragma unroll
        for (int mt = 0; mt < 4; mt++)
            #pragma unroll
            for (int rr = 0; rr < 2; rr++) {
                uint32_t fi = pack_h2(fmaf(acc[mt][0][rr * 2],     0.5f, bFh[0]),
                                      fmaf(acc[mt][0][rr * 2 + 1], 0.5f, bFh[1]));
                __half2 f2 = __hfma2(u2h(tanh_h2(fi)), h05, h05);
                float2 ff = __half22float2(f2);
                uint32_t gi = pack_h2(acc[mt][1][rr * 2] + bG[0],
                                      acc[mt][1][rr * 2 + 1] + bG[1]);
                float2 gg = __half22float2(u2h(tanh_h2(gi)));
                uint32_t oi = pack_h2(fmaf(acc[mt][2][rr * 2],     0.5f, bOh[0]),
                                      fmaf(acc[mt][2][rr * 2 + 1], 0.5f, bOh[1]));
                __half2 o2 = __hfma2(u2h(tanh_h2(oi)), h05, h05);
                float c10 = ff.x * c_r[mt][rr][0] + ig_r[mt][rr][0] * gg.x;
                float c11 = ff.y * c_r[mt][rr][1] + ig_r[mt][rr][1] * gg.y;
                c_r[mt][rr][0] = c10;
                c_r[mt][rr][1] = c11;
                __half2 hv2 = __hmul2(o2, u2h(tanh_h2(pack_h2(c10, c11))));
                uint32_t pk = *(uint32_t*)&hv2;
                int b = r_base + mt * 16 + rr * 8;
                if (t < TT - 1) {
                    *(uint32_t*)(Xo + (size_t)b * KR + hcol) = pk;
                } else {
                    // ---- inline folded head at last step ----
                    float2 hf = __half22float2(hv2);
                    float p = hf.x * wf0 + hf.y * wf1;
                    p += __shfl_xor_sync(0xFFFFFFFFu, p, 1);
                    p += __shfl_xor_sync(0xFFFFFFFFu, p, 2);
                    if ((lane & 3) == 0) atomicAdd(out + b, p);
                }
            }

        // ---- x(t+1) convert BEFORE arrive (ordered by barrier release for peers) ----
        if (jt == 0 && t < TT - 1 && tid < 128) {
            const int b = b_base + tid;
            const float* xr = xg + (size_t)b * (TT * DD) + (size_t)(t + 1) * DD;
            __half* dst = Xo + (size_t)b * KR + HH;
            #pragma unroll
            for (int i = 0; i < 4; i++) {
                float4 v0 = *(const float4*)(xr + i * 8);
                float4 v1 = *(const float4*)(xr + i * 8 + 4);
                uint4 pk = make_uint4(pack_h2(v0.x, v0.y), pack_h2(v0.z, v0.w),
                                      pack_h2(v1.x, v1.y), pack_h2(v1.z, v1.w));
                *(uint4*)(dst + i * 8) = pk;
            }
        }

        // ---- hardware cluster barrier (release/acquire at cluster scope) ----
        if (t < TT - 1) {
            cluster_arrive();
            cluster_wait();
        }
    }

    // ---- pm + bias tail (jt==0 CTAs) ----
    if (jt == 0 && tid < 128) {
        const int b = b_base + tid;
        float s = g_beff;
        #pragma unroll
        for (int k = 0; k < PMM; k++) s += pm[b * PMM + k] * g_weff[HH + k];
        atomicAdd(out + b, s);
    }
}

// ---------------- launch ----------------
extern "C" void kernel_launch(void* const* d_in, const int* in_sizes, int n_in,
                              void* d_out, int out_size)
{
    const float* x       = (const float*)d_in[0];
    const float* latlons = (const float*)d_in[1];
    const float* yearly  = (const float*)d_in[2];
    const float* pm      = (const float*)d_in[3];
    const float* Wf_i    = (const float*)d_in[4];
    const float* Wf_h    = (const float*)d_in[5];
    const float* bf      = (const float*)d_in[6];
    const float* Wu      = (const float*)d_in[7];
    const float* bu      = (const float*)d_in[8];
    const float* Wg_i    = (const float*)d_in[9];
    const float* Wg_h    = (const float*)d_in[10];
    const float* bg      = (const float*)d_in[11];
    const float* Wo_i    = (const float*)d_in[12];
    const float* Wo_h    = (const float*)d_in[13];
    const float* bo      = (const float*)d_in[14];
    const float* Wd0     = (const float*)d_in[15];
    const float* bd0     = (const float*)d_in[16];
    const float* Wd1     = (const float*)d_in[17];
    const float* bd1     = (const float*)d_in[18];

    static bool attr_set = false;
    if (!attr_set) {
        cudaFuncSetAttribute(step_persist, cudaFuncAttributeMaxDynamicSharedMemorySize, SMEM_TOTAL);
        attr_set = true;
    }

    prep_head<<<34, 256>>>(Wd0, bd0, Wd1, bd1, (float*)d_out);

    step_persist<<<dim3(16, 8), 256, SMEM_TOTAL>>>(
        x, latlons, yearly, Wu, bu,
        Wf_i, Wf_h, bf, Wg_i, Wg_h, bg, Wo_i, Wo_h, bo,
        pm, (float*)d_out);
}

// round 15
// speedup vs baseline: 2.0599x; 2.0599x over previous
#include <cuda_runtime.h>
#include <cuda_fp16.h>
#include <math.h>
#include <stdint.h>

#define BB 2048
#define TT 128
#define DD 32
#define HH 256
#define SS 39
#define PMM 12
#define KR 288              /* k layout: [h 256 | x 32] */
#define NCHUNK 2
#define KB 144
#define NK16 18             /* 288/16 */

/* smem layout (bytes) */
#define A_PITCH 304                       /* 152 halfs: 144 data + 8 pad, odd x 16B */
#define A_STAGE (128 * A_PITCH)           /* 38912 */
#define W_ORIGIN (2 * A_STAGE)            /* 77824 */
#define W_PITCH 208                       /* 104 halfs: 96 data + 8 pad */
#define SMEM_TOTAL (W_ORIGIN + KR * W_PITCH)   /* 137728 */

// ---------------- device scratch ----------------
__device__ __half g_X[2][BB * KR];               // activations [b][k], ping-pong
__device__ float g_weff[HH + PMM];
__device__ float g_beff;
__device__ unsigned int g_cnt[16 * 32];          // per-bm monotone arrival counters (128B apart)

// ---------------- asm helpers ----------------
__device__ __forceinline__ uint32_t smem_u32(const void* p) {
    uint32_t a;
    asm("{ .reg .u64 t; cvta.to.shared.u64 t, %1; cvt.u32.u64 %0, t; }" : "=r"(a) : "l"(p));
    return a;
}
__device__ __forceinline__ void cp16(uint32_t dst, const void* src) {
    asm volatile("cp.async.cg.shared.global [%0], [%1], 16;" :: "r"(dst), "l"(src) : "memory");
}
__device__ __forceinline__ void cp_commit() {
    asm volatile("cp.async.commit_group;" ::: "memory");
}
template <int N>
__device__ __forceinline__ void cp_wait() {
    asm volatile("cp.async.wait_group %0;" :: "n"(N) : "memory");
}
__device__ __forceinline__ void ldm_x4(uint32_t* r, uint32_t addr) {
    asm volatile("ldmatrix.sync.aligned.m8n8.x4.shared.b16 {%0,%1,%2,%3}, [%4];"
                 : "=r"(r[0]), "=r"(r[1]), "=r"(r[2]), "=r"(r[3]) : "r"(addr));
}
__device__ __forceinline__ void ldm_x2t(uint32_t* r, uint32_t addr) {
    asm volatile("ldmatrix.sync.aligned.m8n8.x2.trans.shared.b16 {%0,%1}, [%2];"
                 : "=r"(r[0]), "=r"(r[1]) : "r"(addr));
}
__device__ __forceinline__ void mma16816(float* d, const uint32_t* a, const uint32_t* b) {
    asm volatile(
        "mma.sync.aligned.m16n8k16.row.col.f32.f16.f16.f32 "
        "{%0,%1,%2,%3}, {%4,%5,%6,%7}, {%8,%9}, {%0,%1,%2,%3};"
        : "+f"(d[0]), "+f"(d[1]), "+f"(d[2]), "+f"(d[3])
        : "r"(a[0]), "r"(a[1]), "r"(a[2]), "r"(a[3]), "r"(b[0]), "r"(b[1]));
}
__device__ __forceinline__ float tanh_fast(float x) {
    float y;
    asm("tanh.approx.f32 %0, %1;" : "=f"(y) : "f"(x));
    return y;
}
__device__ __forceinline__ float sigmoid_fast(float x) {
    return fmaf(0.5f, tanh_fast(0.5f * x), 0.5f);
}
__device__ __forceinline__ uint32_t tanh_h2(uint32_t x) {
    uint32_t y;
    asm("tanh.approx.f16x2 %0, %1;" : "=r"(y) : "r"(x));
    return y;
}
__device__ __forceinline__ uint32_t pack_h2(float a, float b) {
    __half2 h = __floats2half2_rn(a, b);
    return *(uint32_t*)&h;
}
__device__ __forceinline__ __half2 u2h(uint32_t u) { return *(__half2*)&u; }
__device__ __forceinline__ void red_release(unsigned int* p) {
    asm volatile("red.release.gpu.global.add.u32 [%0], 1;" :: "l"(p) : "memory");
}
__device__ __forceinline__ unsigned int ld_acquire(const unsigned int* p) {
    unsigned int v;
    asm volatile("ld.acquire.gpu.global.u32 %0, [%1];" : "=r"(v) : "l"(p) : "memory");
    return v;
}

// ---------------- prep: warp-parallel head collapse + counters + out zero (34 blocks) ----------------
__global__ void prep_head(const float* __restrict__ Wd0, const float* __restrict__ bd0,
                          const float* __restrict__ Wd1, const float* __restrict__ bd1,
                          float* __restrict__ out)
{
    const int gw = blockIdx.x * 8 + (threadIdx.x >> 5);   // global warp id
    const int lane = threadIdx.x & 31;
    const int gid = blockIdx.x * 256 + threadIdx.x;
    if (gid < BB) out[gid] = 0.0f;
    if (gw < HH + PMM) {
        float s = 0.0f;
        #pragma unroll
        for (int i = 0; i < 8; i++) {
            int m = i * 32 + lane;
            s += Wd1[m] * Wd0[m * (HH + PMM) + gw];
        }
        #pragma unroll
        for (int off = 16; off > 0; off >>= 1)
            s += __shfl_xor_sync(0xFFFFFFFFu, s, off);
        if (lane == 0) g_weff[gw] = s;
    } else if (gw == HH + PMM) {
        float s = 0.0f;
        #pragma unroll
        for (int i = 0; i < 8; i++) {
            int m = i * 32 + lane;
            s += Wd1[m] * bd0[m];
        }
        #pragma unroll
        for (int off = 16; off > 0; off >>= 1)
            s += __shfl_xor_sync(0xFFFFFFFFu, s, off);
        if (lane == 0) g_beff = s + bd1[0];
        if (lane < 16) g_cnt[lane * 32] = 0;
    }
}

// ---------------- persistent recurrent kernel (head folded in) ----------------
__global__ void __launch_bounds__(256, 1) step_persist(
    const float* __restrict__ xg,
    const float* __restrict__ latlons, const float* __restrict__ yearly,
    const float* __restrict__ Wu, const float* __restrict__ bu,
    const float* __restrict__ Wf_i, const float* __restrict__ Wf_h, const float* __restrict__ bf,
    const float* __restrict__ Wg_i, const float* __restrict__ Wg_h, const float* __restrict__ bg,
    const float* __restrict__ Wo_i, const float* __restrict__ Wo_h, const float* __restrict__ bo,
    const float* __restrict__ pm, float* __restrict__ out)
{
    extern __shared__ char smem[];
    const uint32_t sb = smem_u32(smem);
    const int tid = threadIdx.x;
    const int lane = tid & 31;
    const int wid = tid >> 5;
    const int wm = wid & 1;           // 0..1 (64 batch rows)
    const int wn = wid >> 1;          // 0..3 (8 h cols)
    const int bm = blockIdx.x;        // 0..15
    const int jt = blockIdx.y;        // 0..7
    const int b_base = bm * 128;
    const int h0 = jt * 32;

    const int r_base = b_base + wm * 64 + (lane >> 2);    // + mt*16 + rr*8
    const int hcol = h0 + wn * 8 + (lane & 3) * 2;        // 2 consecutive h

    // ---- prologue: W tile gathered DIRECTLY from raw fp32 weights -> SMEM ----
    {
        __half* Wrow = (__half*)(smem + W_ORIGIN);
        #pragma unroll
        for (int ci = 0; ci < 12; ci++) {
            int col = wid * 12 + ci;
            int gate = col >> 5;
            int hh = col & 31;
            const float* Whg = (gate == 0) ? Wf_h : (gate == 1) ? Wg_h : Wo_h;
            const float* Wig = (gate == 0) ? Wf_i : (gate == 1) ? Wg_i : Wo_i;
            const float* hrow = Whg + (size_t)(h0 + hh) * HH;
            const float* irow = Wig + (size_t)(h0 + hh) * DD;
            #pragma unroll
            for (int it = 0; it < 9; it++) {
                int k = it * 32 + lane;
                float v = (k < HH) ? hrow[k] : irow[k - HH];
                Wrow[k * 104 + col] = __float2half(v);
            }
        }
    }

    // ---- prologue: bias (sigmoid ones pre-scaled by 0.5) + head weights ----
    float bFh[2], bG[2], bOh[2];
    #pragma unroll
    for (int cc = 0; cc < 2; cc++) {
        bFh[cc] = bf[hcol + cc] * 0.5f;
        bG[cc]  = bg[hcol + cc];
        bOh[cc] = bo[hcol + cc] * 0.5f;
    }
    const float wf0 = g_weff[hcol];
    const float wf1 = g_weff[hcol + 1];
    const __half2 h05 = __float2half2_rn(0.5f);

    // ---- prologue: i_gate computed in-place into registers, c = 0 ----
    float c_r[4][2][2];
    float ig_r[4][2][2];
    #pragma unroll
    for (int mt = 0; mt < 4; mt++)
        #pragma unroll
        for (int rr = 0; rr < 2; rr++) {
            const int b = r_base + mt * 16 + rr * 8;
            const float ll0 = latlons[b * 2 + 0];
            const float ll1 = latlons[b * 2 + 1];
            const float* yr = yearly + (size_t)b * 37;
            #pragma unroll
            for (int cc = 0; cc < 2; cc++) {
                const int h = hcol + cc;
                const float* w = Wu + h * SS;
                float s = bu[h] + w[0] * ll0 + w[1] * ll1;
                #pragma unroll
                for (int i = 0; i < 37; i++) s += w[2 + i] * yr[i];
                ig_r[mt][rr][cc] = sigmoid_fast(s);
                c_r[mt][rr][cc] = 0.0f;
            }
        }

    // ---- prologue: init X[0] in place ----
    #pragma unroll
    for (int mt = 0; mt < 4; mt++)
        #pragma unroll
        for (int rr = 0; rr < 2; rr++) {
            int b = r_base + mt * 16 + rr * 8;
            *(uint32_t*)(&g_X[0][(size_t)b * KR + hcol]) = 0u;
        }
    if (jt == 0 && tid < 128) {
        const int b = b_base + tid;
        const float* xr = xg + (size_t)b * (TT * DD);
        __half* dst = &g_X[0][(size_t)b * KR + HH];
        #pragma unroll
        for (int i = 0; i < 4; i++) {
            float4 v0 = *(const float4*)(xr + i * 8);
            float4 v1 = *(const float4*)(xr + i * 8 + 4);
            uint4 pk = make_uint4(pack_h2(v0.x, v0.y), pack_h2(v0.z, v0.w),
                                  pack_h2(v1.x, v1.y), pack_h2(v1.z, v1.w));
            *(uint4*)(dst + i * 8) = pk;
        }
    }
    __syncthreads();

    // ---- hoist W fragments into registers (gate = nt) ----
    uint32_t bfrag[NK16][3][2];
    {
        const uint32_t wb = sb + W_ORIGIN + (lane & 15) * W_PITCH + wn * 16;
        #pragma unroll
        for (int k16 = 0; k16 < NK16; k16++)
            #pragma unroll
            for (int gate = 0; gate < 3; gate++)
                ldm_x2t(bfrag[k16][gate], wb + k16 * (16 * W_PITCH) + gate * 64);
    }

    // ---- barrier round 1: X[0] visible across the bm group (per-warp spin) ----
    if (tid == 0) red_release(&g_cnt[bm * 32]);
    if (lane == 0) { while (ld_acquire(&g_cnt[bm * 32]) < 8u) {} }
    __syncwarp();

    const uint32_t a_off = (uint32_t)((wm * 64 + (lane & 15)) * A_PITCH + (lane >> 4) * 16);

    for (int t = 0; t < TT; t++) {
        const __half* __restrict__ Xb = g_X[t & 1];
        __half* Xo = &g_X[(t + 1) & 1][0];

        // ---- on-the-fly x convert for t+1 ----
        if (jt == 0 && t < TT - 1 && tid < 128) {
            const int b = b_base + tid;
            const float* xr = xg + (size_t)b * (TT * DD) + (size_t)(t + 1) * DD;
            __half* dst = Xo + (size_t)b * KR + HH;
            #pragma unroll
            for (int i = 0; i < 4; i++) {
                float4 v0 = *(const float4*)(xr + i * 8);
                float4 v1 = *(const float4*)(xr + i * 8 + 4);
                uint4 pk = make_uint4(pack_h2(v0.x, v0.y), pack_h2(v0.z, v0.w),
                                      pack_h2(v1.x, v1.y), pack_h2(v1.z, v1.w));
                *(uint4*)(dst + i * 8) = pk;
            }
        }

        // ---- issue both A chunks (cp.async.cg: L2-only) ----
        #pragma unroll
        for (int c = 0; c < NCHUNK; c++) {
            #pragma unroll
            for (int i = 0; i < 9; i++) {
                int slot = tid + i * 256;
                int row = slot / 18;
                int cq = slot - row * 18;
                cp16(sb + c * A_STAGE + row * A_PITCH + cq * 16,
                     Xb + (size_t)(b_base + row) * KR + c * KB + cq * 8);
            }
            cp_commit();
        }

        float acc[4][3][4];
        #pragma unroll
        for (int mt = 0; mt < 4; mt++)
            #pragma unroll
            for (int g = 0; g < 3; g++)
                #pragma unroll
                for (int q = 0; q < 4; q++) acc[mt][g][q] = 0.0f;

        // ---- MMA over 2 chunks x 9 k16 ----
        #pragma unroll
        for (int c = 0; c < NCHUNK; c++) {
            if (c == 0) cp_wait<1>();
            else cp_wait<0>();
            __syncthreads();
            const uint32_t aB = sb + c * A_STAGE + a_off;
            #pragma unroll
            for (int kk = 0; kk < 9; kk++) {
                uint32_t af[4][4];
                #pragma unroll
                for (int mt = 0; mt < 4; mt++)
                    ldm_x4(af[mt], aB + mt * (16 * A_PITCH) + kk * 32);
                #pragma unroll
                for (int mt = 0; mt < 4; mt++)
                    #pragma unroll
                    for (int g = 0; g < 3; g++)
                        mma16816(acc[mt][g], af[mt], bfrag[c * 9 + kk][g]);
            }
        }

        // ---- f16x2 epilogue: gates via tanh.approx.f16x2, c stays fp32 ----
        #pragma unroll
        for (int mt = 0; mt < 4; mt++)
            #pragma unroll
            for (int rr = 0; rr < 2; rr++) {
                uint32_t fi = pack_h2(fmaf(acc[mt][0][rr * 2],     0.5f, bFh[0]),
                                      fmaf(acc[mt][0][rr * 2 + 1], 0.5f, bFh[1]));
                __half2 f2 = __hfma2(u2h(tanh_h2(fi)), h05, h05);
                float2 ff = __half22float2(f2);
                uint32_t gi = pack_h2(acc[mt][1][rr * 2] + bG[0],
                                      acc[mt][1][rr * 2 + 1] + bG[1]);
                float2 gg = __half22float2(u2h(tanh_h2(gi)));
                uint32_t oi = pack_h2(fmaf(acc[mt][2][rr * 2],     0.5f, bOh[0]),
                                      fmaf(acc[mt][2][rr * 2 + 1], 0.5f, bOh[1]));
                __half2 o2 = __hfma2(u2h(tanh_h2(oi)), h05, h05);
                float c10 = ff.x * c_r[mt][rr][0] + ig_r[mt][rr][0] * gg.x;
                float c11 = ff.y * c_r[mt][rr][1] + ig_r[mt][rr][1] * gg.y;
                c_r[mt][rr][0] = c10;
                c_r[mt][rr][1] = c11;
                __half2 hv2 = __hmul2(o2, u2h(tanh_h2(pack_h2(c10, c11))));
                uint32_t pk = *(uint32_t*)&hv2;
                int b = r_base + mt * 16 + rr * 8;
                if (t < TT - 1) {
                    *(uint32_t*)(Xo + (size_t)b * KR + hcol) = pk;
                } else {
                    // ---- inline folded head at last step ----
                    float2 hf = __half22float2(hv2);
                    float p = hf.x * wf0 + hf.y * wf1;
                    p += __shfl_xor_sync(0xFFFFFFFFu, p, 1);
                    p += __shfl_xor_sync(0xFFFFFFFFu, p, 2);
                    if ((lane & 3) == 0) atomicAdd(out + b, p);
                }
            }

        // ---- per-bm barrier: sync -> tid0 release -> per-warp acquire spin ----
        if (t < TT - 1) {
            __syncthreads();
            if (tid == 0) red_release(&g_cnt[bm * 32]);
            const unsigned int target = 8u * (unsigned int)(t + 2);
            if (lane == 0) { while (ld_acquire(&g_cnt[bm * 32]) < target) {} }
            __syncwarp();
        }
    }

    // ---- pm + bias tail (jt==0 CTAs) ----
    if (jt == 0 && tid < 128) {
        const int b = b_base + tid;
        float s = g_beff;
        #pragma unroll
        for (int k = 0; k < PMM; k++) s += pm[b * PMM + k] * g_weff[HH + k];
        atomicAdd(out + b, s);
    }
}

// ---------------- launch ----------------
extern "C" void kernel_launch(void* const* d_in, const int* in_sizes, int n_in,
                              void* d_out, int out_size)
{
    const float* x       = (const float*)d_in[0];
    const float* latlons = (const float*)d_in[1];
    const float* yearly  = (const float*)d_in[2];
    const float* pm      = (const float*)d_in[3];
    const float* Wf_i    = (const float*)d_in[4];
    const float* Wf_h    = (const float*)d_in[5];
    const float* bf      = (const float*)d_in[6];
    const float* Wu      = (const float*)d_in[7];
    const float* bu      = (const float*)d_in[8];
    const float* Wg_i    = (const float*)d_in[9];
    const float* Wg_h    = (const float*)d_in[10];
    const float* bg      = (const float*)d_in[11];
    const float* Wo_i    = (const float*)d_in[12];
    const float* Wo_h    = (const float*)d_in[13];
    const float* bo      = (const float*)d_in[14];
    const float* Wd0     = (const float*)d_in[15];
    const float* bd0     = (const float*)d_in[16];
    const float* Wd1     = (const float*)d_in[17];
    const float* bd1     = (const float*)d_in[18];

    static bool attr_set = false;
    if (!attr_set) {
        cudaFuncSetAttribute(step_persist, cudaFuncAttributeMaxDynamicSharedMemorySize, SMEM_TOTAL);
        attr_set = true;
    }

    prep_head<<<34, 256>>>(Wd0, bd0, Wd1, bd1, (float*)d_out);

    step_persist<<<dim3(16, 8), 256, SMEM_TOTAL>>>(
        x, latlons, yearly, Wu, bu,
        Wf_i, Wf_h, bf, Wg_i, Wg_h, bg, Wo_i, Wo_h, bo,
        pm, (float*)d_out);
}

// round 16
// speedup vs baseline: 2.1416x; 1.0397x over previous
#include <cuda_runtime.h>
#include <cuda_fp16.h>
#include <math.h>
#include <stdint.h>

#define BB 2048
#define TT 128
#define DD 32
#define HH 256
#define SS 39
#define PMM 12
#define KR 288              /* k layout: [h 256 | x 32] */
#define NCHUNK 2
#define KB 144
#define NK16 18             /* 288/16 */

/* smem layout (bytes) */
#define A_PITCH 304                       /* 152 halfs: 144 data + 8 pad, odd x 16B */
#define A_STAGE (128 * A_PITCH)           /* 38912 */
#define W_ORIGIN (2 * A_STAGE)            /* 77824 */
#define W_PITCH 208                       /* 104 halfs: 96 data + 8 pad */
#define SMEM_TOTAL (W_ORIGIN + KR * W_PITCH)   /* 137728 */

// ---------------- device scratch ----------------
__device__ __half g_X[2][BB * KR];               // activations [b][k], ping-pong
__device__ float g_weff[HH + PMM];
__device__ float g_beff;
__device__ unsigned int g_cnt[16 * 32];          // per-bm monotone arrival counters (128B apart)

// ---------------- asm helpers ----------------
__device__ __forceinline__ uint32_t smem_u32(const void* p) {
    uint32_t a;
    asm("{ .reg .u64 t; cvta.to.shared.u64 t, %1; cvt.u32.u64 %0, t; }" : "=r"(a) : "l"(p));
    return a;
}
__device__ __forceinline__ void cp16(uint32_t dst, const void* src) {
    asm volatile("cp.async.cg.shared.global [%0], [%1], 16;" :: "r"(dst), "l"(src) : "memory");
}
__device__ __forceinline__ void cp_commit() {
    asm volatile("cp.async.commit_group;" ::: "memory");
}
template <int N>
__device__ __forceinline__ void cp_wait() {
    asm volatile("cp.async.wait_group %0;" :: "n"(N) : "memory");
}
__device__ __forceinline__ void ldm_x4(uint32_t* r, uint32_t addr) {
    asm volatile("ldmatrix.sync.aligned.m8n8.x4.shared.b16 {%0,%1,%2,%3}, [%4];"
                 : "=r"(r[0]), "=r"(r[1]), "=r"(r[2]), "=r"(r[3]) : "r"(addr));
}
__device__ __forceinline__ void ldm_x2t(uint32_t* r, uint32_t addr) {
    asm volatile("ldmatrix.sync.aligned.m8n8.x2.trans.shared.b16 {%0,%1}, [%2];"
                 : "=r"(r[0]), "=r"(r[1]) : "r"(addr));
}
__device__ __forceinline__ void mma16816(float* d, const uint32_t* a, const uint32_t* b) {
    asm volatile(
        "mma.sync.aligned.m16n8k16.row.col.f32.f16.f16.f32 "
        "{%0,%1,%2,%3}, {%4,%5,%6,%7}, {%8,%9}, {%0,%1,%2,%3};"
        : "+f"(d[0]), "+f"(d[1]), "+f"(d[2]), "+f"(d[3])
        : "r"(a[0]), "r"(a[1]), "r"(a[2]), "r"(a[3]), "r"(b[0]), "r"(b[1]));
}
__device__ __forceinline__ float tanh_fast(float x) {
    float y;
    asm("tanh.approx.f32 %0, %1;" : "=f"(y) : "f"(x));
    return y;
}
__device__ __forceinline__ float sigmoid_fast(float x) {
    return fmaf(0.5f, tanh_fast(0.5f * x), 0.5f);
}
__device__ __forceinline__ uint32_t tanh_h2(uint32_t x) {
    uint32_t y;
    asm("tanh.approx.f16x2 %0, %1;" : "=r"(y) : "r"(x));
    return y;
}
__device__ __forceinline__ uint32_t pack_h2(float a, float b) {
    __half2 h = __floats2half2_rn(a, b);
    return *(uint32_t*)&h;
}
__device__ __forceinline__ __half2 u2h(uint32_t u) { return *(__half2*)&u; }
__device__ __forceinline__ void red_release(unsigned int* p) {
    asm volatile("red.release.gpu.global.add.u32 [%0], 1;" :: "l"(p) : "memory");
}
__device__ __forceinline__ unsigned int ld_acquire(const unsigned int* p) {
    unsigned int v;
    asm volatile("ld.acquire.gpu.global.u32 %0, [%1];" : "=r"(v) : "l"(p) : "memory");
    return v;
}

// ---------------- prep: warp-parallel head collapse + counters + out zero (34 blocks) ----------------
__global__ void prep_head(const float* __restrict__ Wd0, const float* __restrict__ bd0,
                          const float* __restrict__ Wd1, const float* __restrict__ bd1,
                          float* __restrict__ out)
{
    const int gw = blockIdx.x * 8 + (threadIdx.x >> 5);   // global warp id
    const int lane = threadIdx.x & 31;
    const int gid = blockIdx.x * 256 + threadIdx.x;
    if (gid < BB) out[gid] = 0.0f;
    if (gw < HH + PMM) {
        float s = 0.0f;
        #pragma unroll
        for (int i = 0; i < 8; i++) {
            int m = i * 32 + lane;
            s += Wd1[m] * Wd0[m * (HH + PMM) + gw];
        }
        #pragma unroll
        for (int off = 16; off > 0; off >>= 1)
            s += __shfl_xor_sync(0xFFFFFFFFu, s, off);
        if (lane == 0) g_weff[gw] = s;
    } else if (gw == HH + PMM) {
        float s = 0.0f;
        #pragma unroll
        for (int i = 0; i < 8; i++) {
            int m = i * 32 + lane;
            s += Wd1[m] * bd0[m];
        }
        #pragma unroll
        for (int off = 16; off > 0; off >>= 1)
            s += __shfl_xor_sync(0xFFFFFFFFu, s, off);
        if (lane == 0) g_beff = s + bd1[0];
        if (lane < 16) g_cnt[lane * 32] = 0;
    }
}

// ---------------- persistent recurrent kernel (head folded in) ----------------
__global__ void __launch_bounds__(256, 1) step_persist(
    const float* __restrict__ xg,
    const float* __restrict__ latlons, const float* __restrict__ yearly,
    const float* __restrict__ Wu, const float* __restrict__ bu,
    const float* __restrict__ Wf_i, const float* __restrict__ Wf_h, const float* __restrict__ bf,
    const float* __restrict__ Wg_i, const float* __restrict__ Wg_h, const float* __restrict__ bg,
    const float* __restrict__ Wo_i, const float* __restrict__ Wo_h, const float* __restrict__ bo,
    const float* __restrict__ pm, float* __restrict__ out)
{
    extern __shared__ char smem[];
    const uint32_t sb = smem_u32(smem);
    const int tid = threadIdx.x;
    const int lane = tid & 31;
    const int wid = tid >> 5;
    const int wm = wid & 1;           // 0..1 (64 batch rows)
    const int wn = wid >> 1;          // 0..3 (8 h cols)
    const int bm = blockIdx.x;        // 0..15
    const int jt = blockIdx.y;        // 0..7
    const int b_base = bm * 128;
    const int h0 = jt * 32;

    const int r_base = b_base + wm * 64 + (lane >> 2);    // + mt*16 + rr*8
    const int hcol = h0 + wn * 8 + (lane & 3) * 2;        // 2 consecutive h

    // distributed x feed: this CTA owns batch rows [b_base + jt*16, +16)
    const int xrow = b_base + jt * 16 + (tid >> 3);       // valid for tid < 128
    const int xq = tid & 7;                               // float4 index within row
    const float* xrow_p = xg + (size_t)xrow * (TT * DD) + xq * 4;
    __half* xdst_base = nullptr;   // set per step

    // ---- prologue: W tile gathered DIRECTLY from raw fp32 weights -> SMEM ----
    {
        __half* Wrow = (__half*)(smem + W_ORIGIN);
        #pragma unroll
        for (int ci = 0; ci < 12; ci++) {
            int col = wid * 12 + ci;
            int gate = col >> 5;
            int hh = col & 31;
            const float* Whg = (gate == 0) ? Wf_h : (gate == 1) ? Wg_h : Wo_h;
            const float* Wig = (gate == 0) ? Wf_i : (gate == 1) ? Wg_i : Wo_i;
            const float* hrow = Whg + (size_t)(h0 + hh) * HH;
            const float* irow = Wig + (size_t)(h0 + hh) * DD;
            #pragma unroll
            for (int it = 0; it < 9; it++) {
                int k = it * 32 + lane;
                float v = (k < HH) ? hrow[k] : irow[k - HH];
                Wrow[k * 104 + col] = __float2half(v);
            }
        }
    }

    // ---- prologue: bias (sigmoid ones pre-scaled by 0.5) + head weights ----
    float bFh[2], bG[2], bOh[2];
    #pragma unroll
    for (int cc = 0; cc < 2; cc++) {
        bFh[cc] = bf[hcol + cc] * 0.5f;
        bG[cc]  = bg[hcol + cc];
        bOh[cc] = bo[hcol + cc] * 0.5f;
    }
    const float wf0 = g_weff[hcol];
    const float wf1 = g_weff[hcol + 1];
    const __half2 h05 = __float2half2_rn(0.5f);

    // ---- prologue: i_gate computed in-place into registers, c = 0 ----
    float c_r[4][2][2];
    float ig_r[4][2][2];
    #pragma unroll
    for (int mt = 0; mt < 4; mt++)
        #pragma unroll
        for (int rr = 0; rr < 2; rr++) {
            const int b = r_base + mt * 16 + rr * 8;
            const float ll0 = latlons[b * 2 + 0];
            const float ll1 = latlons[b * 2 + 1];
            const float* yr = yearly + (size_t)b * 37;
            #pragma unroll
            for (int cc = 0; cc < 2; cc++) {
                const int h = hcol + cc;
                const float* w = Wu + h * SS;
                float s = bu[h] + w[0] * ll0 + w[1] * ll1;
                #pragma unroll
                for (int i = 0; i < 37; i++) s += w[2 + i] * yr[i];
                ig_r[mt][rr][cc] = sigmoid_fast(s);
                c_r[mt][rr][cc] = 0.0f;
            }
        }

    // ---- prologue: init X[0] in place (h zeros by ownership; x slice distributed) ----
    #pragma unroll
    for (int mt = 0; mt < 4; mt++)
        #pragma unroll
        for (int rr = 0; rr < 2; rr++) {
            int b = r_base + mt * 16 + rr * 8;
            *(uint32_t*)(&g_X[0][(size_t)b * KR + hcol]) = 0u;
        }
    if (tid < 128) {
        float4 v = *(const float4*)xrow_p;    // t = 0
        uint2 pk = make_uint2(pack_h2(v.x, v.y), pack_h2(v.z, v.w));
        *(uint2*)(&g_X[0][(size_t)xrow * KR + HH + xq * 4]) = pk;
    }
    __syncthreads();

    // ---- hoist W fragments into registers (gate = nt) ----
    uint32_t bfrag[NK16][3][2];
    {
        const uint32_t wb = sb + W_ORIGIN + (lane & 15) * W_PITCH + wn * 16;
        #pragma unroll
        for (int k16 = 0; k16 < NK16; k16++)
            #pragma unroll
            for (int gate = 0; gate < 3; gate++)
                ldm_x2t(bfrag[k16][gate], wb + k16 * (16 * W_PITCH) + gate * 64);
    }

    // ---- barrier round 1: X[0] visible across the bm group (per-warp spin) ----
    if (tid == 0) red_release(&g_cnt[bm * 32]);
    if (lane == 0) { while (ld_acquire(&g_cnt[bm * 32]) < 8u) {} }
    __syncwarp();

    const uint32_t a_off = (uint32_t)((wm * 64 + (lane & 15)) * A_PITCH + (lane >> 4) * 16);

    for (int t = 0; t < TT; t++) {
        const __half* __restrict__ Xb = g_X[t & 1];
        __half* Xo = &g_X[(t + 1) & 1][0];

        // ---- prefetch x(t+1) slice into registers (pure input, no dependency) ----
        uint32_t xpk0 = 0, xpk1 = 0;
        if (t < TT - 1 && tid < 128) {
            float4 v = *(const float4*)(xrow_p + (size_t)(t + 1) * DD);
            xpk0 = pack_h2(v.x, v.y);
            xpk1 = pack_h2(v.z, v.w);
        }

        // ---- issue both A chunks (cp.async.cg: L2-only) ----
        #pragma unroll
        for (int c = 0; c < NCHUNK; c++) {
            #pragma unroll
            for (int i = 0; i < 9; i++) {
                int slot = tid + i * 256;
                int row = slot / 18;
                int cq = slot - row * 18;
                cp16(sb + c * A_STAGE + row * A_PITCH + cq * 16,
                     Xb + (size_t)(b_base + row) * KR + c * KB + cq * 8);
            }
            cp_commit();
        }

        float acc[4][3][4];
        #pragma unroll
        for (int mt = 0; mt < 4; mt++)
            #pragma unroll
            for (int g = 0; g < 3; g++)
                #pragma unroll
                for (int q = 0; q < 4; q++) acc[mt][g][q] = 0.0f;

        // ---- MMA over 2 chunks x 9 k16 ----
        #pragma unroll
        for (int c = 0; c < NCHUNK; c++) {
            if (c == 0) cp_wait<1>();
            else cp_wait<0>();
            __syncthreads();
            const uint32_t aB = sb + c * A_STAGE + a_off;
            #pragma unroll
            for (int kk = 0; kk < 9; kk++) {
                uint32_t af[4][4];
                #pragma unroll
                for (int mt = 0; mt < 4; mt++)
                    ldm_x4(af[mt], aB + mt * (16 * A_PITCH) + kk * 32);
                #pragma unroll
                for (int mt = 0; mt < 4; mt++)
                    #pragma unroll
                    for (int g = 0; g < 3; g++)
                        mma16816(acc[mt][g], af[mt], bfrag[c * 9 + kk][g]);
            }
        }

        // ---- f16x2 epilogue: gates via tanh.approx.f16x2, c stays fp32 ----
        #pragma unroll
        for (int mt = 0; mt < 4; mt++)
            #pragma unroll
            for (int rr = 0; rr < 2; rr++) {
                uint32_t fi = pack_h2(fmaf(acc[mt][0][rr * 2],     0.5f, bFh[0]),
                                      fmaf(acc[mt][0][rr * 2 + 1], 0.5f, bFh[1]));
                __half2 f2 = __hfma2(u2h(tanh_h2(fi)), h05, h05);
                float2 ff = __half22float2(f2);
                uint32_t gi = pack_h2(acc[mt][1][rr * 2] + bG[0],
                                      acc[mt][1][rr * 2 + 1] + bG[1]);
                float2 gg = __half22float2(u2h(tanh_h2(gi)));
                uint32_t oi = pack_h2(fmaf(acc[mt][2][rr * 2],     0.5f, bOh[0]),
                                      fmaf(acc[mt][2][rr * 2 + 1], 0.5f, bOh[1]));
                __half2 o2 = __hfma2(u2h(tanh_h2(oi)), h05, h05);
                float c10 = ff.x * c_r[mt][rr][0] + ig_r[mt][rr][0] * gg.x;
                float c11 = ff.y * c_r[mt][rr][1] + ig_r[mt][rr][1] * gg.y;
                c_r[mt][rr][0] = c10;
                c_r[mt][rr][1] = c11;
                __half2 hv2 = __hmul2(o2, u2h(tanh_h2(pack_h2(c10, c11))));
                uint32_t pk = *(uint32_t*)&hv2;
                int b = r_base + mt * 16 + rr * 8;
                if (t < TT - 1) {
                    *(uint32_t*)(Xo + (size_t)b * KR + hcol) = pk;
                } else {
                    // ---- inline folded head at last step ----
                    float2 hf = __half22float2(hv2);
                    float p = hf.x * wf0 + hf.y * wf1;
                    p += __shfl_xor_sync(0xFFFFFFFFu, p, 1);
                    p += __shfl_xor_sync(0xFFFFFFFFu, p, 2);
                    if ((lane & 3) == 0) atomicAdd(out + b, p);
                }
            }

        // ---- store prefetched x(t+1) slice (data already in registers) ----
        if (t < TT - 1 && tid < 128) {
            *(uint2*)(Xo + (size_t)xrow * KR + HH + xq * 4) = make_uint2(xpk0, xpk1);
        }

        // ---- per-bm barrier: sync -> tid0 release -> per-warp acquire spin ----
        if (t < TT - 1) {
            __syncthreads();
            if (tid == 0) red_release(&g_cnt[bm * 32]);
            const unsigned int target = 8u * (unsigned int)(t + 2);
            if (lane == 0) { while (ld_acquire(&g_cnt[bm * 32]) < target) {} }
            __syncwarp();
        }
    }

    // ---- pm + bias tail (jt==0 CTAs) ----
    if (jt == 0 && tid < 128) {
        const int b = b_base + tid;
        float s = g_beff;
        #pragma unroll
        for (int k = 0; k < PMM; k++) s += pm[b * PMM + k] * g_weff[HH + k];
        atomicAdd(out + b, s);
    }
}

// ---------------- launch ----------------
extern "C" void kernel_launch(void* const* d_in, const int* in_sizes, int n_in,
                              void* d_out, int out_size)
{
    const float* x       = (const float*)d_in[0];
    const float* latlons = (const float*)d_in[1];
    const float* yearly  = (const float*)d_in[2];
    const float* pm      = (const float*)d_in[3];
    const float* Wf_i    = (const float*)d_in[4];
    const float* Wf_h    = (const float*)d_in[5];
    const float* bf      = (const float*)d_in[6];
    const float* Wu      = (const float*)d_in[7];
    const float* bu      = (const float*)d_in[8];
    const float* Wg_i    = (const float*)d_in[9];
    const float* Wg_h    = (const float*)d_in[10];
    const float* bg      = (const float*)d_in[11];
    const float* Wo_i    = (const float*)d_in[12];
    const float* Wo_h    = (const float*)d_in[13];
    const float* bo      = (const float*)d_in[14];
    const float* Wd0     = (const float*)d_in[15];
    const float* bd0     = (const float*)d_in[16];
    const float* Wd1     = (const float*)d_in[17];
    const float* bd1     = (const float*)d_in[18];

    static bool attr_set = false;
    if (!attr_set) {
        cudaFuncSetAttribute(step_persist, cudaFuncAttributeMaxDynamicSharedMemorySize, SMEM_TOTAL);
        attr_set = true;
    }

    prep_head<<<34, 256>>>(Wd0, bd0, Wd1, bd1, (float*)d_out);

    step_persist<<<dim3(16, 8), 256, SMEM_TOTAL>>>(
        x, latlons, yearly, Wu, bu,
        Wf_i, Wf_h, bf, Wg_i, Wg_h, bg, Wo_i, Wo_h, bo,
        pm, (float*)d_out);
}